// round 10
// baseline (speedup 1.0000x reference)
#include <cuda_runtime.h>
#include <cstdint>

#define T_DIM 1024
#define B_DIM 32
#define D_DIM 512
#define C_DIM 1024
#define BLANK 0

// Output packing (floats): [out (T*B*D)] [out_padding (B*T)] [gloss (B*T)] [new_len (B)]
#define OFF_PAD   ((size_t)T_DIM * B_DIM * D_DIM)
#define OFF_GLOSS (OFF_PAD + (size_t)B_DIM * T_DIM)
#define OFF_LEN   (OFF_GLOSS + (size_t)B_DIM * T_DIM)

// Scratch (device global; no allocations allowed)
__device__ int g_pred[B_DIM * T_DIM];   // pred per (b,t), blank-forced by padding

// ---------------------------------------------------------------------------
// K1v3: argmax over C. Warp handles TWO consecutive rows; all 16 float4
// batched into registers first (up to 16 outstanding LDG.128 per lane),
// then two independent reduce chains.
// ---------------------------------------------------------------------------
__global__ void argmax_kernel(const float* __restrict__ logit,
                              const unsigned char* __restrict__ padding) {
    int warp = (blockIdx.x * blockDim.x + threadIdx.x) >> 5;  // 0..16383
    int lane = threadIdx.x & 31;
    int r0 = warp * 2;
    int r1 = r0 + 1;

    const float4* row0 = reinterpret_cast<const float4*>(logit + (size_t)r0 * C_DIM);
    const float4* row1 = reinterpret_cast<const float4*>(logit + (size_t)r1 * C_DIM);

    float4 v[16];
    #pragma unroll
    for (int k = 0; k < 8; k++) v[k] = row0[lane + 32 * k];
    #pragma unroll
    for (int k = 0; k < 8; k++) v[8 + k] = row1[lane + 32 * k];

    // Two independent reductions (ILP). Lowest index wins on ties.
    float best0 = -3.402823466e+38f, best1 = -3.402823466e+38f;
    int bi0 = 0, bi1 = 0;
    #pragma unroll
    for (int k = 0; k < 8; k++) {
        int base = (lane + 32 * k) * 4;
        // row0 quad
        {
            float4 q = v[k];
            float m01 = q.x; int i01 = base;
            if (q.y > m01) { m01 = q.y; i01 = base + 1; }
            float m23 = q.z; int i23 = base + 2;
            if (q.w > m23) { m23 = q.w; i23 = base + 3; }
            float mq = m01; int iq = i01;
            if (m23 > mq) { mq = m23; iq = i23; }
            if (mq > best0) { best0 = mq; bi0 = iq; }
        }
        // row1 quad
        {
            float4 q = v[8 + k];
            float m01 = q.x; int i01 = base;
            if (q.y > m01) { m01 = q.y; i01 = base + 1; }
            float m23 = q.z; int i23 = base + 2;
            if (q.w > m23) { m23 = q.w; i23 = base + 3; }
            float mq = m01; int iq = i01;
            if (m23 > mq) { mq = m23; iq = i23; }
            if (mq > best1) { best1 = mq; bi1 = iq; }
        }
    }
    #pragma unroll
    for (int off = 16; off; off >>= 1) {
        float ov0 = __shfl_down_sync(0xFFFFFFFFu, best0, off);
        int   oi0 = __shfl_down_sync(0xFFFFFFFFu, bi0, off);
        float ov1 = __shfl_down_sync(0xFFFFFFFFu, best1, off);
        int   oi1 = __shfl_down_sync(0xFFFFFFFFu, bi1, off);
        if (ov0 > best0 || (ov0 == best0 && oi0 < bi0)) { best0 = ov0; bi0 = oi0; }
        if (ov1 > best1 || (ov1 == best1 && oi1 < bi1)) { best1 = ov1; bi1 = oi1; }
    }
    if (lane == 0) {
        int t0 = r0 / B_DIM, b0 = r0 % B_DIM;
        int t1 = r1 / B_DIM, b1 = r1 % B_DIM;
        g_pred[b0 * T_DIM + t0] = padding[b0 * T_DIM + t0] ? BLANK : bi0;
        g_pred[b1 * T_DIM + t1] = padding[b1 * T_DIM + t1] ? BLANK : bi1;
    }
}

// ---------------------------------------------------------------------------
// K23: fused RLE + gather/average. Grid (32, B). Every block redundantly
// computes its batch's run-length structure (two two-level scans, g_pred row
// is L2-resident), then 8 warps x 4 output rows each (two pairs) do the
// bandwidth work. blockIdx.x==0 blocks emit the small outputs.
// ---------------------------------------------------------------------------
__global__ void __launch_bounds__(256)
fused_rle_gather(const float* __restrict__ rep, float* __restrict__ out) {
    int b = blockIdx.y;
    int tid = threadIdx.x;         // 0..255
    int lane = tid & 31;
    int w = tid >> 5;              // warp 0..7

    __shared__ int s_cp[T_DIM];        // compacted predictions
    __shared__ int s_ct[T_DIM];        // compacted original frame index
    __shared__ int s_rs[T_DIM + 1];    // run start (compacted idx); s_rs[len]=nb_total
    __shared__ int s_w[8];
    __shared__ int s_w2[8];

    // ---- phase 1: load pred row, scan mask -> compaction ----
    int4 p4 = reinterpret_cast<const int4*>(g_pred + b * T_DIM)[tid];
    int m0 = p4.x != BLANK, m1 = p4.y != BLANK, m2 = p4.z != BLANK, m3 = p4.w != BLANK;
    int local = m0 + m1 + m2 + m3;

    int v = local;
    #pragma unroll
    for (int o = 1; o < 32; o <<= 1) {
        int x = __shfl_up_sync(0xFFFFFFFFu, v, o);
        if (lane >= o) v += x;
    }
    if (lane == 31) s_w[w] = v;
    reinterpret_cast<int4*>(s_cp)[tid] = make_int4(-1, -1, -1, -1);
    __syncthreads();
    if (tid == 0) {
        int run = 0;
        #pragma unroll
        for (int j = 0; j < 8; j++) { run += s_w[j]; s_w[j] = run; }
    }
    __syncthreads();
    int base = (w ? s_w[w - 1] : 0) + (v - local);   // exclusive start
    int nb_total = s_w[7];

    int d = base;
    if (m0) { s_cp[d] = p4.x; s_ct[d] = 4 * tid;     d++; }
    if (m1) { s_cp[d] = p4.y; s_ct[d] = 4 * tid + 1; d++; }
    if (m2) { s_cp[d] = p4.z; s_ct[d] = 4 * tid + 2; d++; }
    if (m3) { s_cp[d] = p4.w; s_ct[d] = 4 * tid + 3; d++; }
    __syncthreads();

    // ---- phase 2: run-start scan on compacted stream ----
    int i0 = 4 * tid;
    int c0 = s_cp[i0], c1 = s_cp[i0 + 1], c2 = s_cp[i0 + 2], c3 = s_cp[i0 + 3];
    int pm1 = (i0 == 0) ? -2 : s_cp[i0 - 1];
    int st0 = (c0 >= 0) && (c0 != pm1);
    int st1 = (c1 >= 0) && (c1 != c0);
    int st2 = (c2 >= 0) && (c2 != c1);
    int st3 = (c3 >= 0) && (c3 != c2);
    int local2 = st0 + st1 + st2 + st3;

    int v2 = local2;
    #pragma unroll
    for (int o = 1; o < 32; o <<= 1) {
        int x = __shfl_up_sync(0xFFFFFFFFu, v2, o);
        if (lane >= o) v2 += x;
    }
    if (lane == 31) s_w2[w] = v2;
    __syncthreads();
    if (tid == 0) {
        int run = 0;
        #pragma unroll
        for (int j = 0; j < 8; j++) { run += s_w2[j]; s_w2[j] = run; }
    }
    __syncthreads();
    int base2 = (w ? s_w2[w - 1] : 0) + (v2 - local2);
    int new_len = s_w2[7];

    int d2 = base2;
    if (st0) s_rs[d2++] = i0;
    if (st1) s_rs[d2++] = i0 + 1;
    if (st2) s_rs[d2++] = i0 + 2;
    if (st3) s_rs[d2++] = i0 + 3;
    if (tid == 0) s_rs[new_len] = nb_total;
    __syncthreads();

    // ---- small outputs (one block column only) ----
    if (blockIdx.x == 0) {
        #pragma unroll
        for (int j = 0; j < 4; j++) {
            int n = tid + 256 * j;
            float gloss = -1.0f;
            if (n < new_len) gloss = (float)s_cp[s_rs[n]];
            out[OFF_GLOSS + (size_t)b * T_DIM + n] = gloss;
            out[OFF_PAD   + (size_t)b * T_DIM + n] = (n >= new_len) ? 1.0f : 0.0f;
        }
        if (tid == 0) out[OFF_LEN + b] = (float)new_len;
    }

    // ---- phase 3: gather/average. Warp handles 4 rows (two pairs) ----
    int nb0 = blockIdx.x * 8 + w;          // 0..255
    float4 z = make_float4(0.f, 0.f, 0.f, 0.f);

    #pragma unroll
    for (int p = 0; p < 2; p++) {
        int n0 = nb0 + 512 * p;            // p=0: 0..255 ; p=1: 512..767
        int n1 = n0 + 256;                 // p=0: 256..511; p=1: 768..1023

        float4* o0 = reinterpret_cast<float4*>(out + ((size_t)n0 * B_DIM + b) * D_DIM);
        float4* o1 = reinterpret_cast<float4*>(out + ((size_t)n1 * B_DIM + b) * D_DIM);

        bool v0ok = n0 < new_len;
        bool v1ok = n1 < new_len;
        int rs0 = 0, cc0 = 1, rs1 = 0, cc1 = 1;
        if (v0ok) { rs0 = s_rs[n0]; cc0 = s_rs[n0 + 1] - rs0; }
        if (v1ok) { rs1 = s_rs[n1]; cc1 = s_rs[n1 + 1] - rs1; }

        if ((!v0ok || cc0 == 1) && (!v1ok || cc1 == 1)) {
            // Fast path: each valid row is a pure copy of one rep row (MLP=8).
            const float4* r0 = nullptr;
            const float4* r1 = nullptr;
            if (v0ok) {
                int t0 = s_ct[rs0];
                r0 = reinterpret_cast<const float4*>(rep + ((size_t)t0 * B_DIM + b) * D_DIM);
            }
            if (v1ok) {
                int t1 = s_ct[rs1];
                r1 = reinterpret_cast<const float4*>(rep + ((size_t)t1 * B_DIM + b) * D_DIM);
            }
            float4 a0 = z, a1 = z, a2 = z, a3 = z;
            float4 b0 = z, b1 = z, b2 = z, b3 = z;
            if (v0ok) { a0 = r0[lane]; a1 = r0[lane + 32]; a2 = r0[lane + 64]; a3 = r0[lane + 96]; }
            if (v1ok) { b0 = r1[lane]; b1 = r1[lane + 32]; b2 = r1[lane + 64]; b3 = r1[lane + 96]; }
            o0[lane]      = a0; o0[lane + 32] = a1; o0[lane + 64] = a2; o0[lane + 96] = a3;
            o1[lane]      = b0; o1[lane + 32] = b1; o1[lane + 64] = b2; o1[lane + 96] = b3;
            continue;
        }

        // General path: per-row averaging loop.
        #pragma unroll
        for (int r = 0; r < 2; r++) {
            bool valid = r ? v1ok : v0ok;
            int rs = r ? rs1 : rs0;
            int cnt = r ? cc1 : cc0;
            float4* orow = r ? o1 : o0;
            if (!valid) {
                orow[lane] = z; orow[lane + 32] = z; orow[lane + 64] = z; orow[lane + 96] = z;
                continue;
            }
            float4 acc0 = z, acc1 = z, acc2 = z, acc3 = z;
            for (int k = 0; k < cnt; k++) {
                int t = s_ct[rs + k];
                const float4* rrow =
                    reinterpret_cast<const float4*>(rep + ((size_t)t * B_DIM + b) * D_DIM);
                float4 q0 = rrow[lane];
                float4 q1 = rrow[lane + 32];
                float4 q2 = rrow[lane + 64];
                float4 q3 = rrow[lane + 96];
                acc0.x += q0.x; acc0.y += q0.y; acc0.z += q0.z; acc0.w += q0.w;
                acc1.x += q1.x; acc1.y += q1.y; acc1.z += q1.z; acc1.w += q1.w;
                acc2.x += q2.x; acc2.y += q2.y; acc2.z += q2.z; acc2.w += q2.w;
                acc3.x += q3.x; acc3.y += q3.y; acc3.z += q3.z; acc3.w += q3.w;
            }
            float inv = 1.0f / (float)cnt;
            acc0.x *= inv; acc0.y *= inv; acc0.z *= inv; acc0.w *= inv;
            acc1.x *= inv; acc1.y *= inv; acc1.z *= inv; acc1.w *= inv;
            acc2.x *= inv; acc2.y *= inv; acc2.z *= inv; acc2.w *= inv;
            acc3.x *= inv; acc3.y *= inv; acc3.z *= inv; acc3.w *= inv;
            orow[lane]      = acc0;
            orow[lane + 32] = acc1;
            orow[lane + 64] = acc2;
            orow[lane + 96] = acc3;
        }
    }
}

extern "C" void kernel_launch(void* const* d_in, const int* in_sizes, int n_in,
                              void* d_out, int out_size) {
    const float* rep = (const float*)d_in[0];          // [T,B,D] f32
    const float* logit = (const float*)d_in[1];        // [T,B,C] f32
    const unsigned char* padding = (const unsigned char*)d_in[2];  // [B,T] bool
    float* out = (float*)d_out;

    // K1v3: 32768 rows, 2 rows per warp, 8 warps/block -> 2048 blocks
    argmax_kernel<<<(T_DIM * B_DIM) / 16, 256>>>(logit, padding);

    // K23: fused RLE + gather. Grid (32, B), 256 threads, 4 rows/warp.
    dim3 grid(T_DIM / 4 / 8, B_DIM);
    fused_rle_gather<<<grid, 256>>>(rep, out);
}

// round 11
// speedup vs baseline: 1.0434x; 1.0434x over previous
#include <cuda_runtime.h>
#include <cstdint>

#define T_DIM 1024
#define B_DIM 32
#define D_DIM 512
#define C_DIM 1024
#define BLANK 0

// Output packing (floats): [out (T*B*D)] [out_padding (B*T)] [gloss (B*T)] [new_len (B)]
#define OFF_PAD   ((size_t)T_DIM * B_DIM * D_DIM)
#define OFF_GLOSS (OFF_PAD + (size_t)B_DIM * T_DIM)
#define OFF_LEN   (OFF_GLOSS + (size_t)B_DIM * T_DIM)

// Scratch (device global; no allocations allowed)
__device__ int g_pred[B_DIM * T_DIM];   // pred per (b,t), blank-forced by padding

// ---------------------------------------------------------------------------
// K1 (R8 version + streaming loads): argmax over C per (t,b) row. Warp per
// row, 8 float4 batched into regs first, quad-tree reduce. __ldcs: logit is
// read exactly once -> evict-first, keep L2 for rep/out.
// ---------------------------------------------------------------------------
__global__ void argmax_kernel(const float* __restrict__ logit,
                              const unsigned char* __restrict__ padding) {
    int warp = (blockIdx.x * blockDim.x + threadIdx.x) >> 5;
    int lane = threadIdx.x & 31;
    if (warp >= T_DIM * B_DIM) return;
    int t = warp / B_DIM;
    int b = warp % B_DIM;

    const float4* row = reinterpret_cast<const float4*>(logit + (size_t)warp * C_DIM);

    float4 v[8];
    #pragma unroll
    for (int k = 0; k < 8; k++) v[k] = __ldcs(row + lane + 32 * k);

    // Lowest index wins on ties (strictly-greater replaces, ascending order).
    float best = -3.402823466e+38f;
    int bi = 0;
    #pragma unroll
    for (int k = 0; k < 8; k++) {
        int base = (lane + 32 * k) * 4;
        float m01 = v[k].x; int i01 = base;
        if (v[k].y > m01) { m01 = v[k].y; i01 = base + 1; }
        float m23 = v[k].z; int i23 = base + 2;
        if (v[k].w > m23) { m23 = v[k].w; i23 = base + 3; }
        float mq = m01; int iq = i01;
        if (m23 > mq) { mq = m23; iq = i23; }
        if (mq > best) { best = mq; bi = iq; }
    }
    #pragma unroll
    for (int off = 16; off; off >>= 1) {
        float ov = __shfl_down_sync(0xFFFFFFFFu, best, off);
        int   oi = __shfl_down_sync(0xFFFFFFFFu, bi, off);
        if (ov > best || (ov == best && oi < bi)) { best = ov; bi = oi; }
    }
    if (lane == 0) {
        int p = padding[b * T_DIM + t] ? BLANK : bi;
        g_pred[b * T_DIM + t] = p;
    }
}

// ---------------------------------------------------------------------------
// K23: fused RLE + gather/average. Grid (32, B). Every block redundantly
// computes its batch's run-length structure, then 8 warps x 4 output rows
// each (two pairs). Streaming hints on the big rep reads / out writes.
// ---------------------------------------------------------------------------
__global__ void __launch_bounds__(256)
fused_rle_gather(const float* __restrict__ rep, float* __restrict__ out) {
    int b = blockIdx.y;
    int tid = threadIdx.x;         // 0..255
    int lane = tid & 31;
    int w = tid >> 5;              // warp 0..7

    __shared__ int s_cp[T_DIM];        // compacted predictions
    __shared__ int s_ct[T_DIM];        // compacted original frame index
    __shared__ int s_rs[T_DIM + 1];    // run start (compacted idx); s_rs[len]=nb_total
    __shared__ int s_w[8];
    __shared__ int s_w2[8];

    // ---- phase 1: load pred row, scan mask -> compaction ----
    int4 p4 = reinterpret_cast<const int4*>(g_pred + b * T_DIM)[tid];
    int m0 = p4.x != BLANK, m1 = p4.y != BLANK, m2 = p4.z != BLANK, m3 = p4.w != BLANK;
    int local = m0 + m1 + m2 + m3;

    int v = local;
    #pragma unroll
    for (int o = 1; o < 32; o <<= 1) {
        int x = __shfl_up_sync(0xFFFFFFFFu, v, o);
        if (lane >= o) v += x;
    }
    if (lane == 31) s_w[w] = v;
    reinterpret_cast<int4*>(s_cp)[tid] = make_int4(-1, -1, -1, -1);
    __syncthreads();
    if (tid == 0) {
        int run = 0;
        #pragma unroll
        for (int j = 0; j < 8; j++) { run += s_w[j]; s_w[j] = run; }
    }
    __syncthreads();
    int base = (w ? s_w[w - 1] : 0) + (v - local);   // exclusive start
    int nb_total = s_w[7];

    int d = base;
    if (m0) { s_cp[d] = p4.x; s_ct[d] = 4 * tid;     d++; }
    if (m1) { s_cp[d] = p4.y; s_ct[d] = 4 * tid + 1; d++; }
    if (m2) { s_cp[d] = p4.z; s_ct[d] = 4 * tid + 2; d++; }
    if (m3) { s_cp[d] = p4.w; s_ct[d] = 4 * tid + 3; d++; }
    __syncthreads();

    // ---- phase 2: run-start scan on compacted stream ----
    int i0 = 4 * tid;
    int c0 = s_cp[i0], c1 = s_cp[i0 + 1], c2 = s_cp[i0 + 2], c3 = s_cp[i0 + 3];
    int pm1 = (i0 == 0) ? -2 : s_cp[i0 - 1];
    int st0 = (c0 >= 0) && (c0 != pm1);
    int st1 = (c1 >= 0) && (c1 != c0);
    int st2 = (c2 >= 0) && (c2 != c1);
    int st3 = (c3 >= 0) && (c3 != c2);
    int local2 = st0 + st1 + st2 + st3;

    int v2 = local2;
    #pragma unroll
    for (int o = 1; o < 32; o <<= 1) {
        int x = __shfl_up_sync(0xFFFFFFFFu, v2, o);
        if (lane >= o) v2 += x;
    }
    if (lane == 31) s_w2[w] = v2;
    __syncthreads();
    if (tid == 0) {
        int run = 0;
        #pragma unroll
        for (int j = 0; j < 8; j++) { run += s_w2[j]; s_w2[j] = run; }
    }
    __syncthreads();
    int base2 = (w ? s_w2[w - 1] : 0) + (v2 - local2);
    int new_len = s_w2[7];

    int d2 = base2;
    if (st0) s_rs[d2++] = i0;
    if (st1) s_rs[d2++] = i0 + 1;
    if (st2) s_rs[d2++] = i0 + 2;
    if (st3) s_rs[d2++] = i0 + 3;
    if (tid == 0) s_rs[new_len] = nb_total;
    __syncthreads();

    // ---- small outputs (one block column only) ----
    if (blockIdx.x == 0) {
        #pragma unroll
        for (int j = 0; j < 4; j++) {
            int n = tid + 256 * j;
            float gloss = -1.0f;
            if (n < new_len) gloss = (float)s_cp[s_rs[n]];
            out[OFF_GLOSS + (size_t)b * T_DIM + n] = gloss;
            out[OFF_PAD   + (size_t)b * T_DIM + n] = (n >= new_len) ? 1.0f : 0.0f;
        }
        if (tid == 0) out[OFF_LEN + b] = (float)new_len;
    }

    // ---- phase 3: gather/average. Warp handles 4 rows (two pairs) ----
    int nb0 = blockIdx.x * 8 + w;          // 0..255
    float4 z = make_float4(0.f, 0.f, 0.f, 0.f);

    #pragma unroll
    for (int p = 0; p < 2; p++) {
        int n0 = nb0 + 512 * p;            // p=0: 0..255 ; p=1: 512..767
        int n1 = n0 + 256;                 // p=0: 256..511; p=1: 768..1023

        float4* o0 = reinterpret_cast<float4*>(out + ((size_t)n0 * B_DIM + b) * D_DIM);
        float4* o1 = reinterpret_cast<float4*>(out + ((size_t)n1 * B_DIM + b) * D_DIM);

        bool v0ok = n0 < new_len;
        bool v1ok = n1 < new_len;
        int rs0 = 0, cc0 = 1, rs1 = 0, cc1 = 1;
        if (v0ok) { rs0 = s_rs[n0]; cc0 = s_rs[n0 + 1] - rs0; }
        if (v1ok) { rs1 = s_rs[n1]; cc1 = s_rs[n1 + 1] - rs1; }

        if ((!v0ok || cc0 == 1) && (!v1ok || cc1 == 1)) {
            // Fast path: each valid row is a pure copy of one rep row (MLP=8).
            const float4* r0 = nullptr;
            const float4* r1 = nullptr;
            if (v0ok) {
                int t0 = s_ct[rs0];
                r0 = reinterpret_cast<const float4*>(rep + ((size_t)t0 * B_DIM + b) * D_DIM);
            }
            if (v1ok) {
                int t1 = s_ct[rs1];
                r1 = reinterpret_cast<const float4*>(rep + ((size_t)t1 * B_DIM + b) * D_DIM);
            }
            float4 a0 = z, a1 = z, a2 = z, a3 = z;
            float4 b0 = z, b1 = z, b2 = z, b3 = z;
            if (v0ok) {
                a0 = __ldcs(r0 + lane);      a1 = __ldcs(r0 + lane + 32);
                a2 = __ldcs(r0 + lane + 64); a3 = __ldcs(r0 + lane + 96);
            }
            if (v1ok) {
                b0 = __ldcs(r1 + lane);      b1 = __ldcs(r1 + lane + 32);
                b2 = __ldcs(r1 + lane + 64); b3 = __ldcs(r1 + lane + 96);
            }
            __stcs(o0 + lane, a0);      __stcs(o0 + lane + 32, a1);
            __stcs(o0 + lane + 64, a2); __stcs(o0 + lane + 96, a3);
            __stcs(o1 + lane, b0);      __stcs(o1 + lane + 32, b1);
            __stcs(o1 + lane + 64, b2); __stcs(o1 + lane + 96, b3);
            continue;
        }

        // General path: per-row averaging loop.
        #pragma unroll
        for (int r = 0; r < 2; r++) {
            bool valid = r ? v1ok : v0ok;
            int rs = r ? rs1 : rs0;
            int cnt = r ? cc1 : cc0;
            float4* orow = r ? o1 : o0;
            if (!valid) {
                __stcs(orow + lane, z);      __stcs(orow + lane + 32, z);
                __stcs(orow + lane + 64, z); __stcs(orow + lane + 96, z);
                continue;
            }
            float4 acc0 = z, acc1 = z, acc2 = z, acc3 = z;
            for (int k = 0; k < cnt; k++) {
                int t = s_ct[rs + k];
                const float4* rrow =
                    reinterpret_cast<const float4*>(rep + ((size_t)t * B_DIM + b) * D_DIM);
                float4 q0 = __ldcs(rrow + lane);
                float4 q1 = __ldcs(rrow + lane + 32);
                float4 q2 = __ldcs(rrow + lane + 64);
                float4 q3 = __ldcs(rrow + lane + 96);
                acc0.x += q0.x; acc0.y += q0.y; acc0.z += q0.z; acc0.w += q0.w;
                acc1.x += q1.x; acc1.y += q1.y; acc1.z += q1.z; acc1.w += q1.w;
                acc2.x += q2.x; acc2.y += q2.y; acc2.z += q2.z; acc2.w += q2.w;
                acc3.x += q3.x; acc3.y += q3.y; acc3.z += q3.z; acc3.w += q3.w;
            }
            float inv = 1.0f / (float)cnt;
            acc0.x *= inv; acc0.y *= inv; acc0.z *= inv; acc0.w *= inv;
            acc1.x *= inv; acc1.y *= inv; acc1.z *= inv; acc1.w *= inv;
            acc2.x *= inv; acc2.y *= inv; acc2.z *= inv; acc2.w *= inv;
            acc3.x *= inv; acc3.y *= inv; acc3.z *= inv; acc3.w *= inv;
            __stcs(orow + lane, acc0);      __stcs(orow + lane + 32, acc1);
            __stcs(orow + lane + 64, acc2); __stcs(orow + lane + 96, acc3);
        }
    }
}

extern "C" void kernel_launch(void* const* d_in, const int* in_sizes, int n_in,
                              void* d_out, int out_size) {
    const float* rep = (const float*)d_in[0];          // [T,B,D] f32
    const float* logit = (const float*)d_in[1];        // [T,B,C] f32
    const unsigned char* padding = (const unsigned char*)d_in[2];  // [B,T] bool
    float* out = (float*)d_out;

    // K1: 32768 rows, warp per row, 8 rows per 256-thread block
    argmax_kernel<<<(T_DIM * B_DIM) / 8, 256>>>(logit, padding);

    // K23: fused RLE + gather. Grid (32, B), 256 threads, 4 rows/warp.
    dim3 grid(T_DIM / 4 / 8, B_DIM);
    fused_rle_gather<<<grid, 256>>>(rep, out);
}

// round 12
// speedup vs baseline: 1.0475x; 1.0039x over previous
#include <cuda_runtime.h>
#include <cstdint>

#define T_DIM 1024
#define B_DIM 32
#define D_DIM 512
#define C_DIM 1024
#define BLANK 0

// Output packing (floats): [out (T*B*D)] [out_padding (B*T)] [gloss (B*T)] [new_len (B)]
#define OFF_PAD   ((size_t)T_DIM * B_DIM * D_DIM)
#define OFF_GLOSS (OFF_PAD + (size_t)B_DIM * T_DIM)
#define OFF_LEN   (OFF_GLOSS + (size_t)B_DIM * T_DIM)

// Scratch (device global; no allocations allowed)
__device__ int g_pred[B_DIM * T_DIM];   // pred per (b,t), blank-forced by padding

// ---------------------------------------------------------------------------
// K1: argmax over C per (t,b) row. Warp per row, 8 float4 batched into regs,
// quad-tree reduce, __ldcs streaming. Triggers PDL completion after store.
// ---------------------------------------------------------------------------
__global__ void argmax_kernel(const float* __restrict__ logit,
                              const unsigned char* __restrict__ padding) {
    int warp = (blockIdx.x * blockDim.x + threadIdx.x) >> 5;
    int lane = threadIdx.x & 31;
    if (warp >= T_DIM * B_DIM) return;
    int t = warp / B_DIM;
    int b = warp % B_DIM;

    const float4* row = reinterpret_cast<const float4*>(logit + (size_t)warp * C_DIM);

    float4 v[8];
    #pragma unroll
    for (int k = 0; k < 8; k++) v[k] = __ldcs(row + lane + 32 * k);

    // Lowest index wins on ties (strictly-greater replaces, ascending order).
    float best = -3.402823466e+38f;
    int bi = 0;
    #pragma unroll
    for (int k = 0; k < 8; k++) {
        int base = (lane + 32 * k) * 4;
        float m01 = v[k].x; int i01 = base;
        if (v[k].y > m01) { m01 = v[k].y; i01 = base + 1; }
        float m23 = v[k].z; int i23 = base + 2;
        if (v[k].w > m23) { m23 = v[k].w; i23 = base + 3; }
        float mq = m01; int iq = i01;
        if (m23 > mq) { mq = m23; iq = i23; }
        if (mq > best) { best = mq; bi = iq; }
    }
    #pragma unroll
    for (int off = 16; off; off >>= 1) {
        float ov = __shfl_down_sync(0xFFFFFFFFu, best, off);
        int   oi = __shfl_down_sync(0xFFFFFFFFu, bi, off);
        if (ov > best || (ov == best && oi < bi)) { best = ov; bi = oi; }
    }
    if (lane == 0) {
        int p = padding[b * T_DIM + t] ? BLANK : bi;
        g_pred[b * T_DIM + t] = p;
    }
    cudaTriggerProgrammaticLaunchCompletion();
}

// ---------------------------------------------------------------------------
// K23: fused RLE + gather/average. Grid (32, B). PDL: launched while K1
// drains; syncs on grid dependency right before the first g_pred read.
// ---------------------------------------------------------------------------
__global__ void __launch_bounds__(256)
fused_rle_gather(const float* __restrict__ rep, float* __restrict__ out) {
    int b = blockIdx.y;
    int tid = threadIdx.x;         // 0..255
    int lane = tid & 31;
    int w = tid >> 5;              // warp 0..7

    __shared__ int s_cp[T_DIM];        // compacted predictions
    __shared__ int s_ct[T_DIM];        // compacted original frame index
    __shared__ int s_rs[T_DIM + 1];    // run start (compacted idx); s_rs[len]=nb_total
    __shared__ int s_w[8];
    __shared__ int s_w2[8];

    // Prologue that doesn't depend on K1: init compacted stream.
    reinterpret_cast<int4*>(s_cp)[tid] = make_int4(-1, -1, -1, -1);

    // Wait for K1's writes to be visible.
    cudaGridDependencySynchronize();

    // ---- phase 1: load pred row, scan mask -> compaction ----
    int4 p4 = reinterpret_cast<const int4*>(g_pred + b * T_DIM)[tid];
    int m0 = p4.x != BLANK, m1 = p4.y != BLANK, m2 = p4.z != BLANK, m3 = p4.w != BLANK;
    int local = m0 + m1 + m2 + m3;

    int v = local;
    #pragma unroll
    for (int o = 1; o < 32; o <<= 1) {
        int x = __shfl_up_sync(0xFFFFFFFFu, v, o);
        if (lane >= o) v += x;
    }
    if (lane == 31) s_w[w] = v;
    __syncthreads();
    if (tid == 0) {
        int run = 0;
        #pragma unroll
        for (int j = 0; j < 8; j++) { run += s_w[j]; s_w[j] = run; }
    }
    __syncthreads();
    int base = (w ? s_w[w - 1] : 0) + (v - local);   // exclusive start
    int nb_total = s_w[7];

    int d = base;
    if (m0) { s_cp[d] = p4.x; s_ct[d] = 4 * tid;     d++; }
    if (m1) { s_cp[d] = p4.y; s_ct[d] = 4 * tid + 1; d++; }
    if (m2) { s_cp[d] = p4.z; s_ct[d] = 4 * tid + 2; d++; }
    if (m3) { s_cp[d] = p4.w; s_ct[d] = 4 * tid + 3; d++; }
    __syncthreads();

    // ---- phase 2: run-start scan on compacted stream ----
    int i0 = 4 * tid;
    int c0 = s_cp[i0], c1 = s_cp[i0 + 1], c2 = s_cp[i0 + 2], c3 = s_cp[i0 + 3];
    int pm1 = (i0 == 0) ? -2 : s_cp[i0 - 1];
    int st0 = (c0 >= 0) && (c0 != pm1);
    int st1 = (c1 >= 0) && (c1 != c0);
    int st2 = (c2 >= 0) && (c2 != c1);
    int st3 = (c3 >= 0) && (c3 != c2);
    int local2 = st0 + st1 + st2 + st3;

    int v2 = local2;
    #pragma unroll
    for (int o = 1; o < 32; o <<= 1) {
        int x = __shfl_up_sync(0xFFFFFFFFu, v2, o);
        if (lane >= o) v2 += x;
    }
    if (lane == 31) s_w2[w] = v2;
    __syncthreads();
    if (tid == 0) {
        int run = 0;
        #pragma unroll
        for (int j = 0; j < 8; j++) { run += s_w2[j]; s_w2[j] = run; }
    }
    __syncthreads();
    int base2 = (w ? s_w2[w - 1] : 0) + (v2 - local2);
    int new_len = s_w2[7];

    int d2 = base2;
    if (st0) s_rs[d2++] = i0;
    if (st1) s_rs[d2++] = i0 + 1;
    if (st2) s_rs[d2++] = i0 + 2;
    if (st3) s_rs[d2++] = i0 + 3;
    if (tid == 0) s_rs[new_len] = nb_total;
    __syncthreads();

    // ---- small outputs (one block column only) ----
    if (blockIdx.x == 0) {
        #pragma unroll
        for (int j = 0; j < 4; j++) {
            int n = tid + 256 * j;
            float gloss = -1.0f;
            if (n < new_len) gloss = (float)s_cp[s_rs[n]];
            out[OFF_GLOSS + (size_t)b * T_DIM + n] = gloss;
            out[OFF_PAD   + (size_t)b * T_DIM + n] = (n >= new_len) ? 1.0f : 0.0f;
        }
        if (tid == 0) out[OFF_LEN + b] = (float)new_len;
    }

    // ---- phase 3: gather/average. Warp handles 4 rows (two pairs) ----
    int nb0 = blockIdx.x * 8 + w;          // 0..255
    float4 z = make_float4(0.f, 0.f, 0.f, 0.f);

    #pragma unroll
    for (int p = 0; p < 2; p++) {
        int n0 = nb0 + 512 * p;            // p=0: 0..255 ; p=1: 512..767
        int n1 = n0 + 256;                 // p=0: 256..511; p=1: 768..1023

        float4* o0 = reinterpret_cast<float4*>(out + ((size_t)n0 * B_DIM + b) * D_DIM);
        float4* o1 = reinterpret_cast<float4*>(out + ((size_t)n1 * B_DIM + b) * D_DIM);

        bool v0ok = n0 < new_len;
        bool v1ok = n1 < new_len;
        int rs0 = 0, cc0 = 1, rs1 = 0, cc1 = 1;
        if (v0ok) { rs0 = s_rs[n0]; cc0 = s_rs[n0 + 1] - rs0; }
        if (v1ok) { rs1 = s_rs[n1]; cc1 = s_rs[n1 + 1] - rs1; }

        if ((!v0ok || cc0 == 1) && (!v1ok || cc1 == 1)) {
            // Fast path: each valid row is a pure copy of one rep row (MLP=8).
            const float4* r0 = nullptr;
            const float4* r1 = nullptr;
            if (v0ok) {
                int t0 = s_ct[rs0];
                r0 = reinterpret_cast<const float4*>(rep + ((size_t)t0 * B_DIM + b) * D_DIM);
            }
            if (v1ok) {
                int t1 = s_ct[rs1];
                r1 = reinterpret_cast<const float4*>(rep + ((size_t)t1 * B_DIM + b) * D_DIM);
            }
            float4 a0 = z, a1 = z, a2 = z, a3 = z;
            float4 b0 = z, b1 = z, b2 = z, b3 = z;
            if (v0ok) {
                a0 = __ldcs(r0 + lane);      a1 = __ldcs(r0 + lane + 32);
                a2 = __ldcs(r0 + lane + 64); a3 = __ldcs(r0 + lane + 96);
            }
            if (v1ok) {
                b0 = __ldcs(r1 + lane);      b1 = __ldcs(r1 + lane + 32);
                b2 = __ldcs(r1 + lane + 64); b3 = __ldcs(r1 + lane + 96);
            }
            __stcs(o0 + lane, a0);      __stcs(o0 + lane + 32, a1);
            __stcs(o0 + lane + 64, a2); __stcs(o0 + lane + 96, a3);
            __stcs(o1 + lane, b0);      __stcs(o1 + lane + 32, b1);
            __stcs(o1 + lane + 64, b2); __stcs(o1 + lane + 96, b3);
            continue;
        }

        // General path: per-row averaging loop.
        #pragma unroll
        for (int r = 0; r < 2; r++) {
            bool valid = r ? v1ok : v0ok;
            int rs = r ? rs1 : rs0;
            int cnt = r ? cc1 : cc0;
            float4* orow = r ? o1 : o0;
            if (!valid) {
                __stcs(orow + lane, z);      __stcs(orow + lane + 32, z);
                __stcs(orow + lane + 64, z); __stcs(orow + lane + 96, z);
                continue;
            }
            float4 acc0 = z, acc1 = z, acc2 = z, acc3 = z;
            for (int k = 0; k < cnt; k++) {
                int t = s_ct[rs + k];
                const float4* rrow =
                    reinterpret_cast<const float4*>(rep + ((size_t)t * B_DIM + b) * D_DIM);
                float4 q0 = __ldcs(rrow + lane);
                float4 q1 = __ldcs(rrow + lane + 32);
                float4 q2 = __ldcs(rrow + lane + 64);
                float4 q3 = __ldcs(rrow + lane + 96);
                acc0.x += q0.x; acc0.y += q0.y; acc0.z += q0.z; acc0.w += q0.w;
                acc1.x += q1.x; acc1.y += q1.y; acc1.z += q1.z; acc1.w += q1.w;
                acc2.x += q2.x; acc2.y += q2.y; acc2.z += q2.z; acc2.w += q2.w;
                acc3.x += q3.x; acc3.y += q3.y; acc3.z += q3.z; acc3.w += q3.w;
            }
            float inv = 1.0f / (float)cnt;
            acc0.x *= inv; acc0.y *= inv; acc0.z *= inv; acc0.w *= inv;
            acc1.x *= inv; acc1.y *= inv; acc1.z *= inv; acc1.w *= inv;
            acc2.x *= inv; acc2.y *= inv; acc2.z *= inv; acc2.w *= inv;
            acc3.x *= inv; acc3.y *= inv; acc3.z *= inv; acc3.w *= inv;
            __stcs(orow + lane, acc0);      __stcs(orow + lane + 32, acc1);
            __stcs(orow + lane + 64, acc2); __stcs(orow + lane + 96, acc3);
        }
    }
}

extern "C" void kernel_launch(void* const* d_in, const int* in_sizes, int n_in,
                              void* d_out, int out_size) {
    const float* rep = (const float*)d_in[0];          // [T,B,D] f32
    const float* logit = (const float*)d_in[1];        // [T,B,C] f32
    const unsigned char* padding = (const unsigned char*)d_in[2];  // [B,T] bool
    float* out = (float*)d_out;

    // K1: 32768 rows, warp per row, 8 rows per 256-thread block
    argmax_kernel<<<(T_DIM * B_DIM) / 8, 256>>>(logit, padding);

    // K23 with Programmatic Dependent Launch: overlap launch/fill with K1 drain.
    cudaLaunchConfig_t cfg = {};
    cfg.gridDim = dim3(T_DIM / 4 / 8, B_DIM);
    cfg.blockDim = dim3(256);
    cfg.dynamicSmemBytes = 0;
    cfg.stream = 0;  // legacy default stream (same one the harness captures)
    cudaLaunchAttribute attr[1];
    attr[0].id = cudaLaunchAttributeProgrammaticStreamSerialization;
    attr[0].val.programmaticStreamSerializationAllowed = 1;
    cfg.attrs = attr;
    cfg.numAttrs = 1;
    cudaLaunchKernelEx(&cfg, fused_rle_gather, rep, out);
}